// round 17
// baseline (speedup 1.0000x reference)
#include <cuda_runtime.h>
#include <cstdint>
#include <math.h>

#define L_DIM 128
#define D_DIM 64
#define M_DIM 256
#define TPB   512
#define NWARP 16
#define RPG   8      // rows per group

__device__ float g_cenT[D_DIM * M_DIM];   // cen transposed [d][m], original order
__device__ int   g_order[M_DIM];
__device__ int   g_cs[8], g_ce[8];

// ---- helpers ----
__device__ __forceinline__ uint32_t smem_u32(const void* p) {
    uint32_t a;
    asm("{ .reg .u64 t; cvta.to.shared.u64 t, %1; cvt.u32.u64 %0, t; }" : "=r"(a) : "l"(p));
    return a;
}
__device__ __forceinline__ void cp_async16(uint32_t dst, const void* src) {
    asm volatile("cp.async.ca.shared.global [%0], [%1], 16;" :: "r"(dst), "l"(src));
}
#define CP_COMMIT() asm volatile("cp.async.commit_group;" ::: "memory")
#define CP_WAIT0()  asm volatile("cp.async.wait_group 0;" ::: "memory")

__device__ __forceinline__ unsigned long long pk2(float lo, float hi) {
    unsigned long long r;
    asm("mov.b64 %0, {%1, %2};" : "=l"(r) : "f"(lo), "f"(hi));
    return r;
}
__device__ __forceinline__ unsigned long long fma2(unsigned long long a,
                                                   unsigned long long b,
                                                   unsigned long long c) {
    unsigned long long d;
    asm("fma.rn.f32x2 %0, %1, %2, %3;" : "=l"(d) : "l"(a), "l"(b), "l"(c));
    return d;
}
__device__ __forceinline__ void upk2(float& lo, float& hi, unsigned long long v) {
    asm("mov.b64 {%0, %1}, %2;" : "=f"(lo), "=f"(hi) : "l"(v));
}
__device__ __forceinline__ int redux_min_s32(int v) {
    int r;
    asm("redux.sync.min.s32 %0, %1, 0xffffffff;" : "=r"(r) : "r"(v));
    return r;
}
union F4U2 { float4 f; unsigned long long u[2]; };

// ---- fused prep: blocks 0..255 compute cen row; block 256 computes order ----
__global__ void prep_kernel(const float* __restrict__ cfeat,
                            const float* __restrict__ conf,
                            const float* __restrict__ W,
                            const float* __restrict__ bias,
                            const int*   __restrict__ cen_c)
{
    __shared__ int cnt[8], base[8];
    const int tid = threadIdx.x;
    if (blockIdx.x == M_DIM) {
        if (tid < 8) cnt[tid] = 0;
        __syncthreads();
        const int b = cen_c[4 * tid];
        atomicAdd(&cnt[b], 1);
        __syncthreads();
        if (tid == 0) {
            int a = 0;
            for (int bb = 0; bb < 8; bb++) {
                base[bb] = a; g_cs[bb] = a; a += cnt[bb]; g_ce[bb] = a;
            }
        }
        __syncthreads();
        g_order[atomicAdd(&base[b], 1)] = tid;
    } else if (tid < D_DIM) {
        const int m = blockIdx.x, d = tid;
        const float* row = cfeat + m * L_DIM;
        float acc = bias[d];
#pragma unroll 8
        for (int k = 0; k < L_DIM; k++)
            acc = fmaf(row[k], W[k * D_DIM + d], acc);
        g_cenT[d * M_DIM + m] = conf[m] * acc;
    }
}

__global__ __launch_bounds__(TPB, 1)
void main_kernel(const int*   __restrict__ clu_c,
                 const int*   __restrict__ cen_c,
                 const float* __restrict__ feats,
                 const float* __restrict__ bias,
                 const float* __restrict__ Wg,
                 float*       __restrict__ out,
                 int N, int numGroups)
{
    extern __shared__ float sm[];
    float*  W_s     = sm;                           // 8192
    float2* cen2    = (float2*)(W_s + L_DIM*D_DIM); // 16384 floats
    float*  b_s     = (float*)(cen2 + 32 * M_DIM);  // 64
    float*  feats_s = b_s + D_DIM;                  // 16 * 1024 = 16384 (row-major)
    float*  clu_s   = feats_s + NWARP * RPG * L_DIM;// 16 * 512 = 8192
    float*  vbuf    = clu_s + NWARP * RPG * D_DIM;  // 16 * 256 = 4096
    float*  sw_all  = vbuf + NWARP * M_DIM;         // 16 * 8 = 128
    int4*   cm4_s   = (int4*)(sw_all + NWARP * RPG);// 256 int4
    int*    ord_s   = (int*)(cm4_s + M_DIM);        // 256
    int*    cs_s    = ord_s + M_DIM;                // 8
    int*    ce_s    = cs_s + 8;                     // 8
    int*    rmeta   = ce_s + 8;                     // 16 * 40

    const int tid  = threadIdx.x;
    const int warp = tid >> 5;
    const int lane = tid & 31;

    // ---- one-time staging ----
    if (tid < M_DIM) ord_s[tid] = g_order[tid];
    if (tid < 8) { cs_s[tid] = g_cs[tid]; ce_s[tid] = g_ce[tid]; }
    if (tid < D_DIM) b_s[tid] = bias[tid];
    for (int i = tid; i < L_DIM * D_DIM; i += TPB) W_s[i] = Wg[i];
    __syncthreads();   // ord_s ready
    for (int i = tid; i < 32 * M_DIM; i += TPB) {
        const int d2 = i >> 8, j = i & 255;
        cen2[i] = make_float2(g_cenT[(2*d2  )*M_DIM + ord_s[j]],
                              g_cenT[(2*d2+1)*M_DIM + ord_s[j]]);
    }
    if (tid < M_DIM) {
        int4 c = ((const int4*)cen_c)[ord_s[tid]];
        cm4_s[tid] = make_int4(c.y, c.z, c.w, c.y*c.y + c.z*c.z + c.w*c.w);
    }
    __syncthreads();

    // per-warp private slices
    float* fw = feats_s + warp * (RPG * L_DIM);   // row-major feats
    float* cw = clu_s   + warp * (RPG * D_DIM);
    float* vb = vbuf    + warp * M_DIM;
    float* sw = sw_all  + warp * RPG;
    int*   mw = rmeta   + warp * 40;              // rb[8] x[8] y[8] z[8] n2[8]
    const uint32_t fw_u = smem_u32(fw);

    const int stride = gridDim.x * NWARP;
    int g = blockIdx.x * NWARP + warp;

    // ---- prologue: async-load first group's feats + coords ----
    int4 pc4; int pcv = 0;
    if (g < numGroups) {
        const int r0 = g * RPG;
#pragma unroll
        for (int r = 0; r < RPG; r++)
            if (r0 + r < N)
                cp_async16(fw_u + (uint32_t)(r*L_DIM + lane*4)*4,
                           feats + (long long)(r0+r)*L_DIM + lane*4);
        if (lane < RPG && r0 + lane < N) {
            pc4 = ((const int4*)clu_c)[r0 + lane];
            pcv = 1;
        }
    }
    CP_COMMIT();

    // ---- warp-autonomous pipelined group loop ----
    for (; g < numGroups; g += stride) {
        const int row0 = g * RPG;

        CP_WAIT0();
        // commit coords to smem
        if (lane < RPG) {
            if (pcv) {
                mw[lane]      = pc4.x;
                mw[8 + lane]  = pc4.y;
                mw[16 + lane] = pc4.z;
                mw[24 + lane] = pc4.w;
                mw[32 + lane] = pc4.y*pc4.y + pc4.z*pc4.z + pc4.w*pc4.w;
            } else mw[lane] = -1;
        }
        __syncwarp();

        // ---- Phase A: 8 rows x 2 cols per lane, row-major feats ----
        float acc[16];
        {
            const float bx = b_s[2*lane], by = b_s[2*lane+1];
#pragma unroll
            for (int r = 0; r < RPG; r++) { acc[2*r] = bx; acc[2*r+1] = by; }
#pragma unroll 1
            for (int k0 = 0; k0 < L_DIM; k0 += 4) {
                float4 x[RPG];
#pragma unroll
                for (int r = 0; r < RPG; r++)
                    x[r] = *(const float4*)(fw + r*L_DIM + k0);
#pragma unroll
                for (int kk = 0; kk < 4; kk++) {
                    const float2 w2 = *(const float2*)(W_s + (k0+kk)*D_DIM + 2*lane);
#pragma unroll
                    for (int r = 0; r < RPG; r++) {
                        const float xv = (&x[r].x)[kk];
                        acc[2*r]   = fmaf(xv, w2.x, acc[2*r]);
                        acc[2*r+1] = fmaf(xv, w2.y, acc[2*r+1]);
                    }
                }
            }
            // write clu + norms
#pragma unroll
            for (int r = 0; r < RPG; r++)
                *(float2*)(cw + r*D_DIM + 2*lane) = make_float2(acc[2*r], acc[2*r+1]);
            float q[RPG];
#pragma unroll
            for (int r = 0; r < RPG; r++)
                q[r] = acc[2*r]*acc[2*r] + acc[2*r+1]*acc[2*r+1];
#pragma unroll
            for (int off = 16; off; off >>= 1) {
#pragma unroll
                for (int r = 0; r < RPG; r++)
                    q[r] += __shfl_xor_sync(0xffffffffu, q[r], off);
            }
#pragma unroll
            for (int r = 0; r < RPG; r++)
                if (lane == r) sw[r] = 1.0f / fmaxf(sqrtf(q[r]), 1e-12f);
        }
        __syncwarp();

        // ---- issue prefetch for NEXT group (fw no longer read) ----
        {
            const int gn = g + stride;
            pcv = 0;
            if (gn < numGroups) {
                const int r0 = gn * RPG;
#pragma unroll
                for (int r = 0; r < RPG; r++)
                    if (r0 + r < N)
                        cp_async16(fw_u + (uint32_t)(r*L_DIM + lane*4)*4,
                                   feats + (long long)(r0+r)*L_DIM + lane*4);
                if (lane < RPG && r0 + lane < N) {
                    pc4 = ((const int4*)clu_c)[r0 + lane];
                    pcv = 1;
                }
            }
            CP_COMMIT();
        }

        // ---- Phase B: per row; full row built in per-warp smem buffer ----
#pragma unroll 1
        for (int rr = 0; rr < RPG; rr++) {
            const int row = row0 + rr;
            if (row >= N) continue;
            const int rb = mw[rr];
            const int s = cs_s[rb], e = ce_s[rb];
            const int rx = mw[8+rr], ry = mw[16+rr], rz = mw[24+rr], rn2 = mw[32+rr];
            const float* cr = cw + rr * D_DIM;
            const float scale = sw[rr];

            // zero the row buffer
            {
                const float4 z = make_float4(0.f, 0.f, 0.f, 0.f);
                *(float4*)(vb + lane*4)       = z;
                *(float4*)(vb + 128 + lane*4) = z;
            }
            __syncwarp();

            float sumv = 0.f;
            if (rb >= 0 && e > s) {
                const int nc = (e - s + 31) >> 5;

                // pass 1: pure-integer min of squared distance + redux
                int best = 0x7fffffff;
#pragma unroll 1
                for (int c = 0; c < nc; c++) {
                    const int jj = s + (c << 5) + lane;
                    const int j = (jj < e) ? jj : s;
                    const int4 cm = cm4_s[j];
                    const int d2 = rn2 + cm.w - 2*(rx*cm.x + ry*cm.y + rz*cm.z);
                    if (jj < e) best = min(best, d2);
                }
                best = redux_min_s32(best);
                const float dmin = fmaxf(sqrtf((float)best), 0.1f);  // = -max logit

                // pass 2: f32x2 dot + exp, scatter v*e into row buffer, sum
#pragma unroll 1
                for (int c = 0; c < nc; c++) {
                    const int jj = s + (c << 5) + lane;
                    const bool val = jj < e;
                    const int j = val ? jj : s;
                    unsigned long long v01 = 0ull, v23 = 0ull;
#pragma unroll 4
                    for (int i = 0; i < 16; i++) {
                        F4U2 a; a.f = *(const float4*)(cr + 4*i);            // broadcast
                        const unsigned long long cl =
                            *(const unsigned long long*)(cen2 + (2*i  )*M_DIM + j);
                        const unsigned long long ch =
                            *(const unsigned long long*)(cen2 + (2*i+1)*M_DIM + j);
                        v01 = fma2(a.u[0], cl, v01);
                        v23 = fma2(a.u[1], ch, v23);
                    }
                    float vl0, vl1, vh0, vh1;
                    upk2(vl0, vl1, v01); upk2(vh0, vh1, v23);
                    const float v = (vl0 + vl1) + (vh0 + vh1);

                    const int4 cm = cm4_s[j];
                    const int d2 = rn2 + cm.w - 2*(rx*cm.x + ry*cm.y + rz*cm.z);
                    const float dist = fmaxf(sqrtf((float)d2), 0.1f);
                    const float ee = val ? __expf(dmin - dist) : 0.f;
                    if (val) vb[ord_s[jj]] = v * ee;
                    sumv += ee;
                }
#pragma unroll
                for (int off = 16; off; off >>= 1)
                    sumv += __shfl_xor_sync(0xffffffffu, sumv, off);
            }
            __syncwarp();

            // coalesced full-row write (empty batch -> zeros)
            const float rinv = (sumv > 0.f) ? (scale / sumv) : 0.f;
            float* orow = out + (long long)row * M_DIM;
            float4 o0 = *(const float4*)(vb + lane*4);
            float4 o1 = *(const float4*)(vb + 128 + lane*4);
            o0.x *= rinv; o0.y *= rinv; o0.z *= rinv; o0.w *= rinv;
            o1.x *= rinv; o1.y *= rinv; o1.z *= rinv; o1.w *= rinv;
            *(float4*)(orow + lane*4)       = o0;
            *(float4*)(orow + 128 + lane*4) = o1;
            __syncwarp();   // vb reuse for next row
        }
        // no block barrier: everything in the loop is warp-private
    }
}

extern "C" void kernel_launch(void* const* d_in, const int* in_sizes, int n_in,
                              void* d_out, int out_size)
{
    const int*   clu_c = (const int*)  d_in[0];
    const int*   cen_c = (const int*)  d_in[1];
    const float* feats = (const float*)d_in[2];
    const float* cfeat = (const float*)d_in[3];
    const float* conf  = (const float*)d_in[4];
    const float* W     = (const float*)d_in[5];
    const float* bias  = (const float*)d_in[6];
    float* out = (float*)d_out;

    const int N = in_sizes[2] / L_DIM;
    const int numGroups = (N + RPG - 1) / RPG;

    // smem: floats 8192+16384+64+16384+8192+4096+128 = 53440
    //     + ints 1024+256+16+640 = 1936   -> 221504 B
    const size_t SMEM = (size_t)(53440 + 1936) * 4;

    prep_kernel<<<M_DIM + 1, 256>>>(cfeat, conf, W, bias, cen_c);

    cudaFuncSetAttribute(main_kernel,
                         cudaFuncAttributeMaxDynamicSharedMemorySize, (int)SMEM);
    main_kernel<<<148, TPB, SMEM>>>(clu_c, cen_c, feats, bias, W, out, N, numGroups);
}